// round 6
// baseline (speedup 1.0000x reference)
#include <cuda_runtime.h>

// Problem constants (fixed by setup_inputs in the reference)
#define N_TRIALS   8
#define T_TOTAL    600
#define N_NEURONS  30000
#define N_SAMPLES  50
#define MAX_COUNT  200
#define T_USE      500           // T_START_MS=0, T_END_MS=500
#define T_HALF     250
#define N_BINS     16
#define SYNC_COST  10.0
#define EPS_D      1e-7

// BIN_MS = round(1000*b) for b in logspace(-3,0,20) with b < 0.25
__constant__ int c_bins[N_BINS] = {1,1,2,3,4,6,9,13,18,26,38,55,78,113,162,234};

// Scratch (no cudaMalloc allowed)
__device__ float        g_sel[N_SAMPLES * T_USE];
__device__ double       g_fano_ps[N_SAMPLES][N_BINS];
__device__ unsigned int g_ticket = 0;

// ---------------------------------------------------------------------------
// Kernel A: sel[s][t] = sum over masked ids of spikes[trial_s, t, id]
// One warp handles TWO timesteps (t, t+250) -> 2 independent gathers per
// lane per iteration (double the per-lane MLP to hide DRAM latency).
// grid = (N_SAMPLES, 32), block = 256 (8 warps)
// ---------------------------------------------------------------------------
__global__ void __launch_bounds__(256)
gather_kernel(const float* __restrict__ spikes,
              const int*   __restrict__ trials,
              const int*   __restrict__ ids_raw,   // int32 words; may be int64 layout
              const float* __restrict__ mask)
{
    __shared__ int s_ids[MAX_COUNT];

    const int smp = blockIdx.x;
    const int tid = threadIdx.x;

    // Sniff int64 vs int32 layout of sample_ids: if int64 (little-endian),
    // the high 32-bit words (odd indices) of values < 25000 are all zero.
    const bool is64 = (ids_raw[1] == 0 && ids_raw[3] == 0 &&
                       ids_raw[5] == 0 && ids_raw[7] == 0);

    bool m_on = false;
    if (tid < MAX_COUNT) {
        const int idx = smp * MAX_COUNT + tid;
        s_ids[tid] = is64 ? ids_raw[2 * idx] : ids_raw[idx];
        m_on = (mask[idx] != 0.0f);
    }
    // mask is a prefix of ones: count = popcount over the block
    const int cnt = __syncthreads_count(m_on);

    const int tr   = trials[smp];
    const int warp = tid >> 5;
    const int lane = tid & 31;
    const int t0   = blockIdx.y * (blockDim.x >> 5) + warp;   // [0, 256)
    if (t0 >= T_HALF) return;
    const int t1 = t0 + T_HALF;                                // [250, 500)

    const float* __restrict__ row0 =
        spikes + ((size_t)tr * T_TOTAL + (size_t)t0) * N_NEURONS;
    const float* __restrict__ row1 =
        spikes + ((size_t)tr * T_TOTAL + (size_t)t1) * N_NEURONS;

    float a0 = 0.0f, a1 = 0.0f;
    #pragma unroll 2
    for (int j = lane; j < cnt; j += 32) {
        const int id = s_ids[j];
        a0 += __ldg(row0 + id);
        a1 += __ldg(row1 + id);
    }

    #pragma unroll
    for (int o = 16; o > 0; o >>= 1) {
        a0 += __shfl_down_sync(0xFFFFFFFFu, a0, o);
        a1 += __shfl_down_sync(0xFFFFFFFFu, a1, o);
    }

    if (lane == 0) {
        g_sel[smp * T_USE + t0] = a0;
        g_sel[smp * T_USE + t1] = a1;
    }
}

// ---------------------------------------------------------------------------
// Kernel B (fused fano + mse): one block per sample.
// 1) warp-shuffle inclusive prefix scan of the 500-element sel row (exact:
//    all values are small integers in fp32)
// 2) every bin count for all 16 bins is a 2-element difference; warp b
//    reduces bin b, writes per-sample fano to g_fano_ps[smp][b]
// 3) last block (atomic ticket) sums over samples, computes MSE, writes out,
//    resets ticket (deterministic across graph replays)
// grid = N_SAMPLES, block = 512 (16 warps = 16 bins)
// ---------------------------------------------------------------------------
__global__ void __launch_bounds__(512)
fano_mse_kernel(const float* __restrict__ exp_fanos,
                float* __restrict__ out)
{
    __shared__ float P[512];
    __shared__ float warp_sums[16];
    __shared__ bool  s_last;

    const int smp  = blockIdx.x;
    const int tid  = threadIdx.x;
    const int wid  = tid >> 5;
    const int lane = tid & 31;

    // --- inclusive prefix scan (2 syncthreads) ---
    float x = (tid < T_USE) ? g_sel[smp * T_USE + tid] : 0.0f;
    #pragma unroll
    for (int o = 1; o < 32; o <<= 1) {
        const float y = __shfl_up_sync(0xFFFFFFFFu, x, o);
        if (lane >= o) x += y;
    }
    if (lane == 31) warp_sums[wid] = x;
    __syncthreads();
    if (wid == 0 && lane < 16) {
        float s = warp_sums[lane];
        #pragma unroll
        for (int o = 1; o < 16; o <<= 1) {
            const float y = __shfl_up_sync(0x0000FFFFu, s, o);
            if (lane >= o) s += y;
        }
        warp_sums[lane] = s;
    }
    __syncthreads();
    P[tid] = x + ((wid > 0) ? warp_sums[wid - 1] : 0.0f);
    __syncthreads();

    // --- per-bin fano (warp b handles bin b) ---
    const int bs = c_bins[wid];
    const int nb = T_USE / bs;

    double sumc = 0.0, sumc2 = 0.0;
    for (int k = lane; k < nb; k += 32) {
        const float hi = P[k * bs + bs - 1];
        const float lo = (k > 0) ? P[k * bs - 1] : 0.0f;
        const double c = (double)(hi - lo);
        sumc  += c;
        sumc2 += c * c;
    }
    #pragma unroll
    for (int o = 16; o > 0; o >>= 1) {
        sumc  += __shfl_down_sync(0xFFFFFFFFu, sumc,  o);
        sumc2 += __shfl_down_sync(0xFFFFFFFFu, sumc2, o);
    }
    if (lane == 0) {
        const double mean = sumc / (double)nb;
        double var = sumc2 / (double)nb - mean * mean;
        if (var < 0.0) var = 0.0;
        const double m = (mean > EPS_D) ? mean : EPS_D;
        g_fano_ps[smp][wid] = var / m;
    }

    // --- last-block finisher ---
    __syncthreads();
    if (tid == 0) {
        __threadfence();
        const unsigned int tkt = atomicAdd(&g_ticket, 1u);
        s_last = (tkt == (unsigned int)(N_SAMPLES - 1));
    }
    __syncthreads();
    if (!s_last) return;

    if (wid == 0) {
        __threadfence();
        double d2 = 0.0;
        if (lane < N_BINS) {
            double sum = 0.0;
            #pragma unroll 5
            for (int s = 0; s < N_SAMPLES; s++)
                sum += g_fano_ps[s][lane];
            const double fm = sum / (double)N_SAMPLES;
            const double d  = (double)exp_fanos[lane] - fm;
            d2 = d * d;
        }
        #pragma unroll
        for (int o = 16; o > 0; o >>= 1)
            d2 += __shfl_down_sync(0xFFFFFFFFu, d2, o);
        if (lane == 0) {
            out[0] = (float)(SYNC_COST * (d2 / (double)N_BINS));
            g_ticket = 0;   // reset for next graph replay
        }
    }
}

// ---------------------------------------------------------------------------
extern "C" void kernel_launch(void* const* d_in, const int* in_sizes, int n_in,
                              void* d_out, int out_size)
{
    const float* spikes = (const float*)d_in[0];
    const float* expf   = (const float*)d_in[1];
    const int*   trials = (const int*)d_in[2];
    const int*   ids    = (const int*)d_in[3];   // int32 words (layout sniffed)
    const float* mask   = (const float*)d_in[4];
    float* out = (float*)d_out;

    dim3 gridA(N_SAMPLES, (T_HALF + 7) / 8);    // 50 x 32, warp handles 2 t's
    gather_kernel<<<gridA, 256>>>(spikes, trials, ids, mask);
    fano_mse_kernel<<<N_SAMPLES, 512>>>(expf, out);
}